// round 1
// baseline (speedup 1.0000x reference)
#include <cuda_runtime.h>
#include <cstdint>

#define N_ROWS 32768
#define DIN    3000
#define H0     1024
#define H1     256
#define K_CL   20

// Scratch for the hidden activation h = silu(x@W1 + b1)  [N, H0]
__device__ float g_h[(size_t)N_ROWS * H0];

// ---------------------------------------------------------------- helpers
__device__ __forceinline__ uint32_t smem_u32(const void* p) {
    return (uint32_t)__cvta_generic_to_shared(p);
}
__device__ __forceinline__ void cp_async16(uint32_t dst, const void* src, int src_bytes) {
    asm volatile("cp.async.cg.shared.global [%0], [%1], 16, %2;\n"
                 :: "r"(dst), "l"(src), "r"(src_bytes));
}
__device__ __forceinline__ void cp_commit() { asm volatile("cp.async.commit_group;\n"); }
__device__ __forceinline__ void cp_wait0()  { asm volatile("cp.async.wait_group 0;\n"); }
__device__ __forceinline__ uint32_t f2tf(float f) {
    uint32_t u; asm("cvt.rna.tf32.f32 %0, %1;" : "=r"(u) : "f"(f)); return u;
}
__device__ __forceinline__ void mma_tf32(float& d0, float& d1, float& d2, float& d3,
    uint32_t a0, uint32_t a1, uint32_t a2, uint32_t a3, uint32_t b0, uint32_t b1) {
    asm volatile(
        "mma.sync.aligned.m16n8k8.row.col.f32.tf32.tf32.f32 "
        "{%0,%1,%2,%3}, {%4,%5,%6,%7}, {%8,%9}, {%0,%1,%2,%3};"
        : "+f"(d0), "+f"(d1), "+f"(d2), "+f"(d3)
        : "r"(a0), "r"(a1), "r"(a2), "r"(a3), "r"(b0), "r"(b1));
}
__device__ __forceinline__ float silu(float v) {
    return v / (1.0f + __expf(-v));
}

// ---------------------------------------------------------------- GEMM1: h = silu(x @ W1 + b1)
// M=32768, N=1024, K=3000. CTA tile 128x128x16, 256 threads (8 warps, 2x4 grid, 64x32 warp tile)
__global__ __launch_bounds__(256) void gemm1_silu(
    const float* __restrict__ x, const float* __restrict__ W1, const float* __restrict__ b1)
{
    constexpr int BM = 128, BN = 128, BK = 16;
    __shared__ float sA[2][BM][BK + 4];   // stride 20: conflict-free for A-frag pattern
    __shared__ float sB[2][BK][BN + 8];   // stride 136 (== 8 mod 32): conflict-free for B-frag

    const int t = threadIdx.x;
    const int lane = t & 31, warp = t >> 5;
    const int wm = warp >> 2, wn = warp & 3;          // 2 x 4 warps
    const int rowBase = blockIdx.y * BM;
    const int colBase = blockIdx.x * BN;

    float acc[4][4][4];
    #pragma unroll
    for (int i = 0; i < 4; i++)
        #pragma unroll
        for (int j = 0; j < 4; j++)
            #pragma unroll
            for (int r = 0; r < 4; r++) acc[i][j][r] = 0.0f;

    const int ktotal = (DIN + BK - 1) / BK;  // 188 (last tile has 8 valid cols)

    auto load_tile = [&](int buf, int kt) {
        const int k0 = kt * BK;
        // A: 128 rows x 16 cols = 512 float4, 2 per thread
        #pragma unroll
        for (int i = 0; i < 2; i++) {
            int r = (t >> 2) + i * 64;
            int c = (t & 3) * 4;
            int gk = k0 + c;
            const float* src = x + (size_t)(rowBase + r) * DIN + gk;
            cp_async16(smem_u32(&sA[buf][r][c]), src, (gk + 4 <= DIN) ? 16 : 0);
        }
        // B: 16 rows x 128 cols = 512 float4, 2 per thread
        #pragma unroll
        for (int i = 0; i < 2; i++) {
            int r = (t >> 5) + i * 8;
            int c = (t & 31) * 4;
            int gk = k0 + r;
            const float* src = W1 + (size_t)gk * H0 + colBase + c;
            cp_async16(smem_u32(&sB[buf][r][c]), src, (gk < DIN) ? 16 : 0);
        }
        cp_commit();
    };

    load_tile(0, 0);
    int buf = 0;
    for (int kt = 0; kt < ktotal; kt++) {
        cp_wait0();
        __syncthreads();
        if (kt + 1 < ktotal) load_tile(buf ^ 1, kt + 1);

        #pragma unroll
        for (int ks = 0; ks < 2; ks++) {
            uint32_t af[4][4], bf[4][2];
            #pragma unroll
            for (int mt = 0; mt < 4; mt++) {
                int row = wm * 64 + mt * 16 + (lane >> 2);
                int c = ks * 8 + (lane & 3);
                af[mt][0] = f2tf(sA[buf][row][c]);
                af[mt][1] = f2tf(sA[buf][row + 8][c]);
                af[mt][2] = f2tf(sA[buf][row][c + 4]);
                af[mt][3] = f2tf(sA[buf][row + 8][c + 4]);
            }
            #pragma unroll
            for (int nt = 0; nt < 4; nt++) {
                int col = wn * 32 + nt * 8 + (lane >> 2);
                int r = ks * 8 + (lane & 3);
                bf[nt][0] = f2tf(sB[buf][r][col]);
                bf[nt][1] = f2tf(sB[buf][r + 4][col]);
            }
            #pragma unroll
            for (int mt = 0; mt < 4; mt++)
                #pragma unroll
                for (int nt = 0; nt < 4; nt++)
                    mma_tf32(acc[mt][nt][0], acc[mt][nt][1], acc[mt][nt][2], acc[mt][nt][3],
                             af[mt][0], af[mt][1], af[mt][2], af[mt][3],
                             bf[nt][0], bf[nt][1]);
        }
        buf ^= 1;
    }

    // epilogue: bias + SiLU -> g_h
    #pragma unroll
    for (int mt = 0; mt < 4; mt++) {
        #pragma unroll
        for (int nt = 0; nt < 4; nt++) {
            int row = rowBase + wm * 64 + mt * 16 + (lane >> 2);
            int col = colBase + wn * 32 + nt * 8 + (lane & 3) * 2;
            float bb0 = __ldg(&b1[col]), bb1 = __ldg(&b1[col + 1]);
            float v0 = acc[mt][nt][0] + bb0, v1 = acc[mt][nt][1] + bb1;
            float v2 = acc[mt][nt][2] + bb0, v3 = acc[mt][nt][3] + bb1;
            float2 o0 = make_float2(silu(v0), silu(v1));
            float2 o1 = make_float2(silu(v2), silu(v3));
            *(float2*)&g_h[(size_t)row * H0 + col] = o0;
            *(float2*)&g_h[(size_t)(row + 8) * H0 + col] = o1;
        }
    }
}

// ---------------------------------------------------------------- GEMM2: z = h @ W2 + b2
// M=32768, N=256 (full), K=1024. CTA tile 64x256x16, 256 threads (2x4 warps, 32x64 warp tile)
__global__ __launch_bounds__(256) void gemm2_z(
    const float* __restrict__ W2, const float* __restrict__ b2, float* __restrict__ zout)
{
    constexpr int BM = 64, BN = 256, BK = 16;
    __shared__ float sA[2][BM][BK + 4];   // stride 20
    __shared__ float sB[2][BK][BN + 8];   // stride 264 (== 8 mod 32)

    const int t = threadIdx.x;
    const int lane = t & 31, warp = t >> 5;
    const int wm = warp >> 2, wn = warp & 3;  // 2 x 4
    const int rowBase = blockIdx.y * BM;

    float acc[2][8][4];
    #pragma unroll
    for (int i = 0; i < 2; i++)
        #pragma unroll
        for (int j = 0; j < 8; j++)
            #pragma unroll
            for (int r = 0; r < 4; r++) acc[i][j][r] = 0.0f;

    const int ktotal = 1024 / BK;  // 64

    auto load_tile = [&](int buf, int kt) {
        const int k0 = kt * BK;
        // A: 64 x 16 = 256 float4, 1 per thread
        {
            int r = t >> 2;
            int c = (t & 3) * 4;
            const float* src = g_h + (size_t)(rowBase + r) * H0 + k0 + c;
            cp_async16(smem_u32(&sA[buf][r][c]), src, 16);
        }
        // B: 16 x 256 = 1024 float4, 4 per thread
        #pragma unroll
        for (int i = 0; i < 4; i++) {
            int idx = t + i * 256;
            int r = idx >> 6;
            int c = (idx & 63) * 4;
            const float* src = W2 + (size_t)(k0 + r) * H1 + c;
            cp_async16(smem_u32(&sB[buf][r][c]), src, 16);
        }
        cp_commit();
    };

    load_tile(0, 0);
    int buf = 0;
    for (int kt = 0; kt < ktotal; kt++) {
        cp_wait0();
        __syncthreads();
        if (kt + 1 < ktotal) load_tile(buf ^ 1, kt + 1);

        #pragma unroll
        for (int ks = 0; ks < 2; ks++) {
            uint32_t af[2][4], bf[8][2];
            #pragma unroll
            for (int mt = 0; mt < 2; mt++) {
                int row = wm * 32 + mt * 16 + (lane >> 2);
                int c = ks * 8 + (lane & 3);
                af[mt][0] = f2tf(sA[buf][row][c]);
                af[mt][1] = f2tf(sA[buf][row + 8][c]);
                af[mt][2] = f2tf(sA[buf][row][c + 4]);
                af[mt][3] = f2tf(sA[buf][row + 8][c + 4]);
            }
            #pragma unroll
            for (int nt = 0; nt < 8; nt++) {
                int col = wn * 64 + nt * 8 + (lane >> 2);
                int r = ks * 8 + (lane & 3);
                bf[nt][0] = f2tf(sB[buf][r][col]);
                bf[nt][1] = f2tf(sB[buf][r + 4][col]);
            }
            #pragma unroll
            for (int mt = 0; mt < 2; mt++)
                #pragma unroll
                for (int nt = 0; nt < 8; nt++)
                    mma_tf32(acc[mt][nt][0], acc[mt][nt][1], acc[mt][nt][2], acc[mt][nt][3],
                             af[mt][0], af[mt][1], af[mt][2], af[mt][3],
                             bf[nt][0], bf[nt][1]);
        }
        buf ^= 1;
    }

    // epilogue: + b2 -> zout
    #pragma unroll
    for (int mt = 0; mt < 2; mt++) {
        #pragma unroll
        for (int nt = 0; nt < 8; nt++) {
            int row = rowBase + wm * 32 + mt * 16 + (lane >> 2);
            int col = wn * 64 + nt * 8 + (lane & 3) * 2;
            float bb0 = __ldg(&b2[col]), bb1 = __ldg(&b2[col + 1]);
            float2 o0 = make_float2(acc[mt][nt][0] + bb0, acc[mt][nt][1] + bb1);
            float2 o1 = make_float2(acc[mt][nt][2] + bb0, acc[mt][nt][3] + bb1);
            *(float2*)&zout[(size_t)row * H1 + col] = o0;
            *(float2*)&zout[(size_t)(row + 8) * H1 + col] = o1;
        }
    }
}

// ---------------------------------------------------------------- soft assign (V=1 -> q = 1/(1+d2), normalized)
__global__ __launch_bounds__(256) void soft_assign(
    const float* __restrict__ z, const float* __restrict__ clusters, float* __restrict__ q)
{
    __shared__ float scl[K_CL][H1];
    int t = threadIdx.x;
    for (int i = t; i < K_CL * H1; i += 256)
        scl[i / H1][i % H1] = clusters[i];
    __syncthreads();

    int warp = t >> 5, lane = t & 31;
    int row = blockIdx.x * 8 + warp;

    float zv[8];
    #pragma unroll
    for (int j = 0; j < 8; j++)
        zv[j] = z[(size_t)row * H1 + lane + 32 * j];

    float qk[K_CL];
    float qsum = 0.0f;
    #pragma unroll
    for (int k = 0; k < K_CL; k++) {
        float s = 0.0f;
        #pragma unroll
        for (int j = 0; j < 8; j++) {
            float d = zv[j] - scl[k][lane + 32 * j];
            s += d * d;
        }
        #pragma unroll
        for (int off = 16; off > 0; off >>= 1)
            s += __shfl_xor_sync(0xffffffffu, s, off);
        qk[k] = 1.0f / (1.0f + s);   // V=1: (1+d2/V)^(-(V+1)/2) = 1/(1+d2)
        qsum += qk[k];
    }
    if (lane == 0) {
        float inv = 1.0f / qsum;
        #pragma unroll
        for (int k = 0; k < K_CL; k++)
            q[(size_t)row * K_CL + k] = qk[k] * inv;
    }
}

// ---------------------------------------------------------------- launch
extern "C" void kernel_launch(void* const* d_in, const int* in_sizes, int n_in,
                              void* d_out, int out_size)
{
    const float* x        = (const float*)d_in[0];
    const float* W1       = (const float*)d_in[1];
    const float* b1       = (const float*)d_in[2];
    const float* W2       = (const float*)d_in[3];
    const float* b2       = (const float*)d_in[4];
    const float* clusters = (const float*)d_in[5];

    float* out = (float*)d_out;
    float* z = out;                                 // [N, H1]
    float* q = out + (size_t)N_ROWS * H1;           // [N, K]

    gemm1_silu<<<dim3(H0 / 128, N_ROWS / 128), 256>>>(x, W1, b1);
    gemm2_z<<<dim3(1, N_ROWS / 64), 256>>>(W2, b2, z);
    soft_assign<<<N_ROWS / 8, 256>>>(z, clusters, q);
}

// round 8
// speedup vs baseline: 2.0260x; 2.0260x over previous
#include <cuda_runtime.h>
#include <cuda_fp16.h>
#include <cstdint>

#define N_ROWS 32768
#define DIN    3000
#define DINP   3008
#define H0     1024
#define H1     256
#define K_CL   20

// Scratch (device globals; allocation-free)
__device__ __half g_xh [(size_t)N_ROWS * DINP];  // x  -> fp16, padded       [N][3008]
__device__ __half g_w1t[(size_t)H0 * DINP];      // W1^T -> fp16, padded     [1024][3008]
__device__ __half g_h  [(size_t)N_ROWS * H0];    // h = silu(x@W1+b1), fp16  [N][1024]
__device__ __half g_w2t[(size_t)H1 * H0];        // W2^T -> fp16             [256][1024]

// ---------------------------------------------------------------- helpers
__device__ __forceinline__ uint32_t smem_u32(const void* p) {
    return (uint32_t)__cvta_generic_to_shared(p);
}
__device__ __forceinline__ void cp_async16(uint32_t dst, const void* src) {
    asm volatile("cp.async.cg.shared.global [%0], [%1], 16;\n" :: "r"(dst), "l"(src));
}
__device__ __forceinline__ void cp_commit() { asm volatile("cp.async.commit_group;\n"); }
__device__ __forceinline__ float silu(float v) { return v / (1.0f + __expf(-v)); }

__device__ __forceinline__ void ldm_x4(uint32_t& r0, uint32_t& r1, uint32_t& r2, uint32_t& r3,
                                       uint32_t addr) {
    asm volatile("ldmatrix.sync.aligned.m8n8.x4.shared.b16 {%0,%1,%2,%3}, [%4];"
                 : "=r"(r0), "=r"(r1), "=r"(r2), "=r"(r3) : "r"(addr));
}
__device__ __forceinline__ void mma16816(float* d, const uint32_t* a, const uint32_t* b) {
    asm volatile(
        "mma.sync.aligned.m16n8k16.row.col.f32.f16.f16.f32 "
        "{%0,%1,%2,%3}, {%4,%5,%6,%7}, {%8,%9}, {%0,%1,%2,%3};"
        : "+f"(d[0]), "+f"(d[1]), "+f"(d[2]), "+f"(d[3])
        : "r"(a[0]), "r"(a[1]), "r"(a[2]), "r"(a[3]), "r"(b[0]), "r"(b[1]));
}

// ---------------------------------------------------------------- prepasses
// x [N,3000] f32 -> g_xh [N,3008] fp16 (zero-padded)
__global__ __launch_bounds__(256) void x_prep(const float* __restrict__ x) {
    size_t idx = (size_t)blockIdx.x * 256 + threadIdx.x;
    if (idx >= (size_t)N_ROWS * (DINP / 8)) return;
    size_t row = idx / (DINP / 8);
    int    c   = (int)(idx % (DINP / 8));     // 8-elem chunk
    __half2 h[4];
    if (c < DIN / 8) {                        // 3000/8 = 375 exact
        const float4* s = (const float4*)(x + row * DIN + c * 8);
        float4 v0 = __ldg(s), v1 = __ldg(s + 1);
        h[0] = __floats2half2_rn(v0.x, v0.y);
        h[1] = __floats2half2_rn(v0.z, v0.w);
        h[2] = __floats2half2_rn(v1.x, v1.y);
        h[3] = __floats2half2_rn(v1.z, v1.w);
    } else {
        h[0] = h[1] = h[2] = h[3] = __floats2half2_rn(0.f, 0.f);
    }
    *(uint4*)(g_xh + row * DINP + c * 8) = *(uint4*)h;
}

// W1 [3000,1024] -> g_w1t [1024,3008] fp16 (transposed, zero-padded)
__global__ void w1t_prep(const float* __restrict__ W1) {
    __shared__ float t[32][33];
    int kb = blockIdx.x * 32, cb = blockIdx.y * 32;
    int tx = threadIdx.x, ty = threadIdx.y;     // 32 x 8
    #pragma unroll
    for (int i = ty; i < 32; i += 8) {
        int k = kb + i;
        t[i][tx] = (k < DIN) ? W1[(size_t)k * H0 + cb + tx] : 0.0f;
    }
    __syncthreads();
    #pragma unroll
    for (int i = ty; i < 32; i += 8)
        g_w1t[(size_t)(cb + i) * DINP + kb + tx] = __float2half_rn(t[tx][i]);
}

// W2 [1024,256] -> g_w2t [256,1024] fp16 (transposed)
__global__ void w2t_prep(const float* __restrict__ W2) {
    __shared__ float t[32][33];
    int kb = blockIdx.x * 32, cb = blockIdx.y * 32;
    int tx = threadIdx.x, ty = threadIdx.y;
    #pragma unroll
    for (int i = ty; i < 32; i += 8)
        t[i][tx] = W2[(size_t)(kb + i) * H1 + cb + tx];
    __syncthreads();
    #pragma unroll
    for (int i = ty; i < 32; i += 8)
        g_w2t[(size_t)(cb + i) * H0 + kb + tx] = __float2half_rn(t[tx][i]);
}

// ---------------------------------------------------------------- GEMM1: h = silu(x@W1+b1)
// M=32768, N=1024, K=3008. BM=128, BN=128, BK=64, 3-stage cp.async, 8 warps (2x4), warp 64x32.
static constexpr int S1 = 3;
struct SM1 { __half A[S1][128][72]; __half B[S1][128][72]; };   // 110,592 B

__global__ __launch_bounds__(256, 2) void gemm1(const float* __restrict__ b1)
{
    extern __shared__ char smraw[];
    SM1& sm = *(SM1*)smraw;
    const int tid = threadIdx.x, lane = tid & 31, warp = tid >> 5;
    const int wm = warp >> 2, wn = warp & 3;
    const int rowBase = blockIdx.y * 128, colBase = blockIdx.x * 128;

    float acc[4][4][4];
    #pragma unroll
    for (int i = 0; i < 4; i++)
        #pragma unroll
        for (int j = 0; j < 4; j++)
            #pragma unroll
            for (int r = 0; r < 4; r++) acc[i][j][r] = 0.0f;

    auto load_tile = [&](int slot, int kt) {
        const int k0 = kt * 64;
        #pragma unroll
        for (int i = 0; i < 4; i++) {
            int idx = i * 256 + tid, r = idx >> 3, ch = idx & 7;
            cp_async16(smem_u32(&sm.A[slot][r][ch * 8]),
                       g_xh + (size_t)(rowBase + r) * DINP + k0 + ch * 8);
        }
        #pragma unroll
        for (int i = 0; i < 4; i++) {
            int idx = i * 256 + tid, r = idx >> 3, ch = idx & 7;
            cp_async16(smem_u32(&sm.B[slot][r][ch * 8]),
                       g_w1t + (size_t)(colBase + r) * DINP + k0 + ch * 8);
        }
        cp_commit();
    };

    const int KT = DINP / 64;   // 47
    load_tile(0, 0);
    load_tile(1, 1);

    // ldmatrix lane addressing (constant per thread)
    const int aRow = lane & 15, aCh = (lane >> 4) * 8;                       // A groups
    const int bRow = (lane & 7) | ((lane & 16) >> 1), bCh = (lane & 8);      // B groups (bCh*? -> *1 = 8 halves)

    for (int kt = 0; kt < KT; kt++) {
        if (kt + 2 < KT) asm volatile("cp.async.wait_group 1;\n" ::: "memory");
        else             asm volatile("cp.async.wait_group 0;\n" ::: "memory");
        __syncthreads();
        if (kt + 2 < KT) load_tile((kt + 2) % S1, kt + 2);

        const int slot = kt % S1;
        #pragma unroll
        for (int ks = 0; ks < 4; ks++) {
            uint32_t af[4][4], bf[4][2];
            #pragma unroll
            for (int mt = 0; mt < 4; mt++)
                ldm_x4(af[mt][0], af[mt][1], af[mt][2], af[mt][3],
                       smem_u32(&sm.A[slot][wm * 64 + mt * 16 + aRow][ks * 16 + aCh]));
            #pragma unroll
            for (int p = 0; p < 2; p++) {
                uint32_t r0, r1, r2, r3;
                ldm_x4(r0, r1, r2, r3,
                       smem_u32(&sm.B[slot][wn * 32 + p * 16 + bRow][ks * 16 + bCh]));
                bf[2 * p][0] = r0; bf[2 * p][1] = r1;
                bf[2 * p + 1][0] = r2; bf[2 * p + 1][1] = r3;
            }
            #pragma unroll
            for (int mt = 0; mt < 4; mt++)
                #pragma unroll
                for (int nt = 0; nt < 4; nt++)
                    mma16816(acc[mt][nt], af[mt], bf[nt]);
        }
    }

    // epilogue: bias + SiLU -> g_h (fp16)
    #pragma unroll
    for (int mt = 0; mt < 4; mt++) {
        #pragma unroll
        for (int nt = 0; nt < 4; nt++) {
            int r = rowBase + wm * 64 + mt * 16 + (lane >> 2);
            int c = colBase + wn * 32 + nt * 8 + (lane & 3) * 2;
            float bb0 = __ldg(&b1[c]), bb1 = __ldg(&b1[c + 1]);
            __half2 h0 = __floats2half2_rn(silu(acc[mt][nt][0] + bb0), silu(acc[mt][nt][1] + bb1));
            __half2 h1 = __floats2half2_rn(silu(acc[mt][nt][2] + bb0), silu(acc[mt][nt][3] + bb1));
            *(__half2*)&g_h[(size_t)r * H0 + c] = h0;
            *(__half2*)&g_h[(size_t)(r + 8) * H0 + c] = h1;
        }
    }
}

// ---------------------------------------------------------------- GEMM2 + soft assign (fused)
// z = h @ W2 + b2  (BM=64, BN=256=H1, BK=64, 2-stage), then q per CTA-owned rows.
struct SM2 { __half A[2][64][72]; __half B[2][256][72]; float scl[K_CL][H1]; };  // 112,640 B

__global__ __launch_bounds__(256, 2) void gemm2_fused(
    const float* __restrict__ b2, const float* __restrict__ clusters,
    float* __restrict__ zout, float* __restrict__ qout)
{
    extern __shared__ char smraw[];
    SM2& sm = *(SM2*)smraw;
    const int tid = threadIdx.x, lane = tid & 31, warp = tid >> 5;
    const int wm = warp >> 2, wn = warp & 3;     // 2 x 4, warp tile 32x64
    const int rowBase = blockIdx.y * 64;

    float acc[2][8][4];
    #pragma unroll
    for (int i = 0; i < 2; i++)
        #pragma unroll
        for (int j = 0; j < 8; j++)
            #pragma unroll
            for (int r = 0; r < 4; r++) acc[i][j][r] = 0.0f;

    auto load_tile = [&](int slot, int kt) {
        const int k0 = kt * 64;
        #pragma unroll
        for (int i = 0; i < 2; i++) {
            int idx = i * 256 + tid, r = idx >> 3, ch = idx & 7;
            cp_async16(smem_u32(&sm.A[slot][r][ch * 8]),
                       g_h + (size_t)(rowBase + r) * H0 + k0 + ch * 8);
        }
        #pragma unroll
        for (int i = 0; i < 8; i++) {
            int idx = i * 256 + tid, r = idx >> 3, ch = idx & 7;
            cp_async16(smem_u32(&sm.B[slot][r][ch * 8]),
                       g_w2t + (size_t)r * H0 + k0 + ch * 8);
        }
        cp_commit();
    };

    load_tile(0, 0);
    // clusters -> smem (overlaps the first cp.async)
    for (int i = tid; i < K_CL * H1; i += 256)
        sm.scl[i / H1][i % H1] = clusters[i];

    const int aRow = lane & 15, aCh = (lane >> 4) * 8;
    const int bRow = (lane & 7) | ((lane & 16) >> 1), bCh = (lane & 8);

    const int KT = H0 / 64;   // 16
    for (int kt = 0; kt < KT; kt++) {
        asm volatile("cp.async.wait_group 0;\n" ::: "memory");
        __syncthreads();
        if (kt + 1 < KT) load_tile((kt + 1) & 1, kt + 1);

        const int slot = kt & 1;
        #pragma unroll
        for (int ks = 0; ks < 4; ks++) {
            uint32_t af[2][4], bf[8][2];
            #pragma unroll
            for (int mt = 0; mt < 2; mt++)
                ldm_x4(af[mt][0], af[mt][1], af[mt][2], af[mt][3],
                       smem_u32(&sm.A[slot][wm * 32 + mt * 16 + aRow][ks * 16 + aCh]));
            #pragma unroll
            for (int p = 0; p < 4; p++) {
                uint32_t r0, r1, r2, r3;
                ldm_x4(r0, r1, r2, r3,
                       smem_u32(&sm.B[slot][wn * 64 + p * 16 + bRow][ks * 16 + bCh]));
                bf[2 * p][0] = r0; bf[2 * p][1] = r1;
                bf[2 * p + 1][0] = r2; bf[2 * p + 1][1] = r3;
            }
            #pragma unroll
            for (int mt = 0; mt < 2; mt++)
                #pragma unroll
                for (int nt = 0; nt < 8; nt++)
                    mma16816(acc[mt][nt], af[mt], bf[nt]);
        }
    }

    // epilogue: z = acc + b2 -> gmem (f32 output)
    #pragma unroll
    for (int mt = 0; mt < 2; mt++) {
        #pragma unroll
        for (int nt = 0; nt < 8; nt++) {
            int r = rowBase + wm * 32 + mt * 16 + (lane >> 2);
            int c = wn * 64 + nt * 8 + (lane & 3) * 2;
            float bb0 = __ldg(&b2[c]), bb1 = __ldg(&b2[c + 1]);
            float2 o0 = make_float2(acc[mt][nt][0] + bb0, acc[mt][nt][1] + bb1);
            float2 o1 = make_float2(acc[mt][nt][2] + bb0, acc[mt][nt][3] + bb1);
            *(float2*)&zout[(size_t)r * H1 + c] = o0;
            *(float2*)&zout[(size_t)(r + 8) * H1 + c] = o1;
        }
    }
    __syncthreads();   // z writes visible block-wide; scl loaded

    // soft assign: V=1 -> q = 1/(1+d2), row-normalized. 8 warps x 8 rows.
    #pragma unroll
    for (int j = 0; j < 8; j++) {
        int row = rowBase + warp * 8 + j;
        float zv[8];
        #pragma unroll
        for (int i = 0; i < 8; i++)
            zv[i] = zout[(size_t)row * H1 + lane + 32 * i];
        float qk[K_CL], qsum = 0.0f;
        #pragma unroll
        for (int k = 0; k < K_CL; k++) {
            float s = 0.0f;
            #pragma unroll
            for (int i = 0; i < 8; i++) {
                float d = zv[i] - sm.scl[k][lane + 32 * i];
                s += d * d;
            }
            #pragma unroll
            for (int off = 16; off > 0; off >>= 1)
                s += __shfl_xor_sync(0xffffffffu, s, off);
            qk[k] = 1.0f / (1.0f + s);
            qsum += qk[k];
        }
        if (lane == 0) {
            float inv = 1.0f / qsum;
            #pragma unroll
            for (int k = 0; k < K_CL; k++)
                qout[(size_t)row * K_CL + k] = qk[k] * inv;
        }
    }
}

// ---------------------------------------------------------------- launch
extern "C" void kernel_launch(void* const* d_in, const int* in_sizes, int n_in,
                              void* d_out, int out_size)
{
    const float* x        = (const float*)d_in[0];
    const float* W1       = (const float*)d_in[1];
    const float* b1       = (const float*)d_in[2];
    const float* W2       = (const float*)d_in[3];
    const float* b2       = (const float*)d_in[4];
    const float* clusters = (const float*)d_in[5];

    float* out = (float*)d_out;
    float* z = out;                            // [N, H1]
    float* q = out + (size_t)N_ROWS * H1;      // [N, K]

    static bool attr_set = false;
    if (!attr_set) {
        cudaFuncSetAttribute(gemm1, cudaFuncAttributeMaxDynamicSharedMemorySize, (int)sizeof(SM1));
        cudaFuncSetAttribute(gemm2_fused, cudaFuncAttributeMaxDynamicSharedMemorySize, (int)sizeof(SM2));
        attr_set = true;
    }

    x_prep<<<(int)(((size_t)N_ROWS * (DINP / 8) + 255) / 256), 256>>>(x);
    w1t_prep<<<dim3(DINP / 32, H0 / 32), dim3(32, 8)>>>(W1);
    w2t_prep<<<dim3(H0 / 32, H1 / 32), dim3(32, 8)>>>(W2);
    gemm1<<<dim3(H0 / 128, N_ROWS / 128), 256, sizeof(SM1)>>>(b1);
    gemm2_fused<<<dim3(1, N_ROWS / 64), 256, sizeof(SM2)>>>(b2, clusters, z, q);
}

// round 10
// speedup vs baseline: 2.0270x; 1.0005x over previous
#include <cuda_runtime.h>
#include <cuda_fp16.h>
#include <cstdint>

#define N_ROWS 32768
#define DIN    3000
#define DINP   3008
#define H0     1024
#define H1     256
#define K_CL   20

// Scratch (device globals; allocation-free)
__device__ __half g_xh [(size_t)N_ROWS * DINP];  // x  -> fp16, padded       [N][3008]
__device__ __half g_w1t[(size_t)H0 * DINP];      // W1^T -> fp16, padded     [1024][3008]
__device__ __half g_h  [(size_t)N_ROWS * H0];    // h = silu(x@W1+b1), fp16  [N][1024]
__device__ __half g_w2t[(size_t)H1 * H0];        // W2^T -> fp16             [256][1024]

// ---------------------------------------------------------------- helpers
__device__ __forceinline__ uint32_t smem_u32(const void* p) {
    return (uint32_t)__cvta_generic_to_shared(p);
}
__device__ __forceinline__ void cp_async16(uint32_t dst, const void* src) {
    asm volatile("cp.async.cg.shared.global [%0], [%1], 16;\n" :: "r"(dst), "l"(src));
}
__device__ __forceinline__ void cp_commit() { asm volatile("cp.async.commit_group;\n"); }
__device__ __forceinline__ float silu(float v) { return v / (1.0f + __expf(-v)); }

__device__ __forceinline__ void ldm_x4(uint32_t& r0, uint32_t& r1, uint32_t& r2, uint32_t& r3,
                                       uint32_t addr) {
    asm volatile("ldmatrix.sync.aligned.m8n8.x4.shared.b16 {%0,%1,%2,%3}, [%4];"
                 : "=r"(r0), "=r"(r1), "=r"(r2), "=r"(r3) : "r"(addr));
}
__device__ __forceinline__ void mma16816(float* d, const uint32_t* a, const uint32_t* b) {
    asm volatile(
        "mma.sync.aligned.m16n8k16.row.col.f32.f16.f16.f32 "
        "{%0,%1,%2,%3}, {%4,%5,%6,%7}, {%8,%9}, {%0,%1,%2,%3};"
        : "+f"(d[0]), "+f"(d[1]), "+f"(d[2]), "+f"(d[3])
        : "r"(a[0]), "r"(a[1]), "r"(a[2]), "r"(a[3]), "r"(b[0]), "r"(b[1]));
}

// ---------------------------------------------------------------- prepasses
// x [N,3000] f32 -> g_xh [N,3008] fp16 (zero-padded)
__global__ __launch_bounds__(256) void x_prep(const float* __restrict__ x) {
    size_t idx = (size_t)blockIdx.x * 256 + threadIdx.x;
    if (idx >= (size_t)N_ROWS * (DINP / 8)) return;
    size_t row = idx / (DINP / 8);
    int    c   = (int)(idx % (DINP / 8));     // 8-elem chunk
    __half2 h[4];
    if (c < DIN / 8) {                        // 3000/8 = 375 exact
        const float4* s = (const float4*)(x + row * DIN + c * 8);
        float4 v0 = __ldg(s), v1 = __ldg(s + 1);
        h[0] = __floats2half2_rn(v0.x, v0.y);
        h[1] = __floats2half2_rn(v0.z, v0.w);
        h[2] = __floats2half2_rn(v1.x, v1.y);
        h[3] = __floats2half2_rn(v1.z, v1.w);
    } else {
        h[0] = h[1] = h[2] = h[3] = __floats2half2_rn(0.f, 0.f);
    }
    *(uint4*)(g_xh + row * DINP + c * 8) = *(uint4*)h;
}

// W1 [3000,1024] -> g_w1t [1024,3008] fp16 (transposed, zero-padded)
__global__ void w1t_prep(const float* __restrict__ W1) {
    __shared__ float t[32][33];
    int kb = blockIdx.x * 32, cb = blockIdx.y * 32;
    int tx = threadIdx.x, ty = threadIdx.y;     // 32 x 8
    #pragma unroll
    for (int i = ty; i < 32; i += 8) {
        int k = kb + i;
        t[i][tx] = (k < DIN) ? W1[(size_t)k * H0 + cb + tx] : 0.0f;
    }
    __syncthreads();
    #pragma unroll
    for (int i = ty; i < 32; i += 8)
        g_w1t[(size_t)(cb + i) * DINP + kb + tx] = __float2half_rn(t[tx][i]);
}

// W2 [1024,256] -> g_w2t [256,1024] fp16 (transposed)
__global__ void w2t_prep(const float* __restrict__ W2) {
    __shared__ float t[32][33];
    int kb = blockIdx.x * 32, cb = blockIdx.y * 32;
    int tx = threadIdx.x, ty = threadIdx.y;
    #pragma unroll
    for (int i = ty; i < 32; i += 8)
        t[i][tx] = W2[(size_t)(kb + i) * H1 + cb + tx];
    __syncthreads();
    #pragma unroll
    for (int i = ty; i < 32; i += 8)
        g_w2t[(size_t)(cb + i) * H0 + kb + tx] = __float2half_rn(t[tx][i]);
}

// ---------------------------------------------------------------- GEMM1: h = silu(x@W1+b1)
// M=32768, N=1024, K=3008. BM=128, BN=128, BK=64, 3-stage cp.async, 8 warps (2x4), warp 64x32.
static constexpr int S1 = 3;
struct SM1 { __half A[S1][128][72]; __half B[S1][128][72]; };   // 110,592 B

__global__ __launch_bounds__(256, 2) void gemm1(const float* __restrict__ b1)
{
    extern __shared__ char smraw[];
    SM1& sm = *(SM1*)smraw;
    const int tid = threadIdx.x, lane = tid & 31, warp = tid >> 5;
    const int wm = warp >> 2, wn = warp & 3;
    const int rowBase = blockIdx.y * 128, colBase = blockIdx.x * 128;

    float acc[4][4][4];
    #pragma unroll
    for (int i = 0; i < 4; i++)
        #pragma unroll
        for (int j = 0; j < 4; j++)
            #pragma unroll
            for (int r = 0; r < 4; r++) acc[i][j][r] = 0.0f;

    auto load_tile = [&](int slot, int kt) {
        const int k0 = kt * 64;
        #pragma unroll
        for (int i = 0; i < 4; i++) {
            int idx = i * 256 + tid, r = idx >> 3, ch = idx & 7;
            cp_async16(smem_u32(&sm.A[slot][r][ch * 8]),
                       g_xh + (size_t)(rowBase + r) * DINP + k0 + ch * 8);
        }
        #pragma unroll
        for (int i = 0; i < 4; i++) {
            int idx = i * 256 + tid, r = idx >> 3, ch = idx & 7;
            cp_async16(smem_u32(&sm.B[slot][r][ch * 8]),
                       g_w1t + (size_t)(colBase + r) * DINP + k0 + ch * 8);
        }
        cp_commit();
    };

    const int KT = DINP / 64;   // 47
    load_tile(0, 0);
    load_tile(1, 1);

    // ldmatrix lane addressing (constant per thread)
    const int aRow = lane & 15, aCh = (lane >> 4) * 8;                       // A groups
    const int bRow = (lane & 7) | ((lane & 16) >> 1), bCh = (lane & 8);      // B groups (bCh*? -> *1 = 8 halves)

    for (int kt = 0; kt < KT; kt++) {
        if (kt + 2 < KT) asm volatile("cp.async.wait_group 1;\n" ::: "memory");
        else             asm volatile("cp.async.wait_group 0;\n" ::: "memory");
        __syncthreads();
        if (kt + 2 < KT) load_tile((kt + 2) % S1, kt + 2);

        const int slot = kt % S1;
        #pragma unroll
        for (int ks = 0; ks < 4; ks++) {
            uint32_t af[4][4], bf[4][2];
            #pragma unroll
            for (int mt = 0; mt < 4; mt++)
                ldm_x4(af[mt][0], af[mt][1], af[mt][2], af[mt][3],
                       smem_u32(&sm.A[slot][wm * 64 + mt * 16 + aRow][ks * 16 + aCh]));
            #pragma unroll
            for (int p = 0; p < 2; p++) {
                uint32_t r0, r1, r2, r3;
                ldm_x4(r0, r1, r2, r3,
                       smem_u32(&sm.B[slot][wn * 32 + p * 16 + bRow][ks * 16 + bCh]));
                bf[2 * p][0] = r0; bf[2 * p][1] = r1;
                bf[2 * p + 1][0] = r2; bf[2 * p + 1][1] = r3;
            }
            #pragma unroll
            for (int mt = 0; mt < 4; mt++)
                #pragma unroll
                for (int nt = 0; nt < 4; nt++)
                    mma16816(acc[mt][nt], af[mt], bf[nt]);
        }
    }

    // epilogue: bias + SiLU -> g_h (fp16)
    #pragma unroll
    for (int mt = 0; mt < 4; mt++) {
        #pragma unroll
        for (int nt = 0; nt < 4; nt++) {
            int r = rowBase + wm * 64 + mt * 16 + (lane >> 2);
            int c = colBase + wn * 32 + nt * 8 + (lane & 3) * 2;
            float bb0 = __ldg(&b1[c]), bb1 = __ldg(&b1[c + 1]);
            __half2 h0 = __floats2half2_rn(silu(acc[mt][nt][0] + bb0), silu(acc[mt][nt][1] + bb1));
            __half2 h1 = __floats2half2_rn(silu(acc[mt][nt][2] + bb0), silu(acc[mt][nt][3] + bb1));
            *(__half2*)&g_h[(size_t)r * H0 + c] = h0;
            *(__half2*)&g_h[(size_t)(r + 8) * H0 + c] = h1;
        }
    }
}

// ---------------------------------------------------------------- GEMM2 + soft assign (fused)
// z = h @ W2 + b2  (BM=64, BN=256=H1, BK=64, 2-stage), then q per CTA-owned rows.
struct SM2 { __half A[2][64][72]; __half B[2][256][72]; float scl[K_CL][H1]; };  // 112,640 B

__global__ __launch_bounds__(256, 2) void gemm2_fused(
    const float* __restrict__ b2, const float* __restrict__ clusters,
    float* __restrict__ zout, float* __restrict__ qout)
{
    extern __shared__ char smraw[];
    SM2& sm = *(SM2*)smraw;
    const int tid = threadIdx.x, lane = tid & 31, warp = tid >> 5;
    const int wm = warp >> 2, wn = warp & 3;     // 2 x 4, warp tile 32x64
    const int rowBase = blockIdx.y * 64;

    float acc[2][8][4];
    #pragma unroll
    for (int i = 0; i < 2; i++)
        #pragma unroll
        for (int j = 0; j < 8; j++)
            #pragma unroll
            for (int r = 0; r < 4; r++) acc[i][j][r] = 0.0f;

    auto load_tile = [&](int slot, int kt) {
        const int k0 = kt * 64;
        #pragma unroll
        for (int i = 0; i < 2; i++) {
            int idx = i * 256 + tid, r = idx >> 3, ch = idx & 7;
            cp_async16(smem_u32(&sm.A[slot][r][ch * 8]),
                       g_h + (size_t)(rowBase + r) * H0 + k0 + ch * 8);
        }
        #pragma unroll
        for (int i = 0; i < 8; i++) {
            int idx = i * 256 + tid, r = idx >> 3, ch = idx & 7;
            cp_async16(smem_u32(&sm.B[slot][r][ch * 8]),
                       g_w2t + (size_t)r * H0 + k0 + ch * 8);
        }
        cp_commit();
    };

    load_tile(0, 0);
    // clusters -> smem (overlaps the first cp.async)
    for (int i = tid; i < K_CL * H1; i += 256)
        sm.scl[i / H1][i % H1] = clusters[i];

    const int aRow = lane & 15, aCh = (lane >> 4) * 8;
    const int bRow = (lane & 7) | ((lane & 16) >> 1), bCh = (lane & 8);

    const int KT = H0 / 64;   // 16
    for (int kt = 0; kt < KT; kt++) {
        asm volatile("cp.async.wait_group 0;\n" ::: "memory");
        __syncthreads();
        if (kt + 1 < KT) load_tile((kt + 1) & 1, kt + 1);

        const int slot = kt & 1;
        #pragma unroll
        for (int ks = 0; ks < 4; ks++) {
            uint32_t af[2][4], bf[8][2];
            #pragma unroll
            for (int mt = 0; mt < 2; mt++)
                ldm_x4(af[mt][0], af[mt][1], af[mt][2], af[mt][3],
                       smem_u32(&sm.A[slot][wm * 32 + mt * 16 + aRow][ks * 16 + aCh]));
            #pragma unroll
            for (int p = 0; p < 4; p++) {
                uint32_t r0, r1, r2, r3;
                ldm_x4(r0, r1, r2, r3,
                       smem_u32(&sm.B[slot][wn * 64 + p * 16 + bRow][ks * 16 + bCh]));
                bf[2 * p][0] = r0; bf[2 * p][1] = r1;
                bf[2 * p + 1][0] = r2; bf[2 * p + 1][1] = r3;
            }
            #pragma unroll
            for (int mt = 0; mt < 2; mt++)
                #pragma unroll
                for (int nt = 0; nt < 8; nt++)
                    mma16816(acc[mt][nt], af[mt], bf[nt]);
        }
    }

    // epilogue: z = acc + b2 -> gmem (f32 output)
    #pragma unroll
    for (int mt = 0; mt < 2; mt++) {
        #pragma unroll
        for (int nt = 0; nt < 8; nt++) {
            int r = rowBase + wm * 32 + mt * 16 + (lane >> 2);
            int c = wn * 64 + nt * 8 + (lane & 3) * 2;
            float bb0 = __ldg(&b2[c]), bb1 = __ldg(&b2[c + 1]);
            float2 o0 = make_float2(acc[mt][nt][0] + bb0, acc[mt][nt][1] + bb1);
            float2 o1 = make_float2(acc[mt][nt][2] + bb0, acc[mt][nt][3] + bb1);
            *(float2*)&zout[(size_t)r * H1 + c] = o0;
            *(float2*)&zout[(size_t)(r + 8) * H1 + c] = o1;
        }
    }
    __syncthreads();   // z writes visible block-wide; scl loaded

    // soft assign: V=1 -> q = 1/(1+d2), row-normalized. 8 warps x 8 rows.
    #pragma unroll
    for (int j = 0; j < 8; j++) {
        int row = rowBase + warp * 8 + j;
        float zv[8];
        #pragma unroll
        for (int i = 0; i < 8; i++)
            zv[i] = zout[(size_t)row * H1 + lane + 32 * i];
        float qk[K_CL], qsum = 0.0f;
        #pragma unroll
        for (int k = 0; k < K_CL; k++) {
            float s = 0.0f;
            #pragma unroll
            for (int i = 0; i < 8; i++) {
                float d = zv[i] - sm.scl[k][lane + 32 * i];
                s += d * d;
            }
            #pragma unroll
            for (int off = 16; off > 0; off >>= 1)
                s += __shfl_xor_sync(0xffffffffu, s, off);
            qk[k] = 1.0f / (1.0f + s);
            qsum += qk[k];
        }
        if (lane == 0) {
            float inv = 1.0f / qsum;
            #pragma unroll
            for (int k = 0; k < K_CL; k++)
                qout[(size_t)row * K_CL + k] = qk[k] * inv;
        }
    }
}

// ---------------------------------------------------------------- launch
extern "C" void kernel_launch(void* const* d_in, const int* in_sizes, int n_in,
                              void* d_out, int out_size)
{
    const float* x        = (const float*)d_in[0];
    const float* W1       = (const float*)d_in[1];
    const float* b1       = (const float*)d_in[2];
    const float* W2       = (const float*)d_in[3];
    const float* b2       = (const float*)d_in[4];
    const float* clusters = (const float*)d_in[5];

    float* out = (float*)d_out;
    float* z = out;                            // [N, H1]
    float* q = out + (size_t)N_ROWS * H1;      // [N, K]

    static bool attr_set = false;
    if (!attr_set) {
        cudaFuncSetAttribute(gemm1, cudaFuncAttributeMaxDynamicSharedMemorySize, (int)sizeof(SM1));
        cudaFuncSetAttribute(gemm2_fused, cudaFuncAttributeMaxDynamicSharedMemorySize, (int)sizeof(SM2));
        attr_set = true;
    }

    x_prep<<<(int)(((size_t)N_ROWS * (DINP / 8) + 255) / 256), 256>>>(x);
    w1t_prep<<<dim3(DINP / 32, H0 / 32), dim3(32, 8)>>>(W1);
    w2t_prep<<<dim3(H0 / 32, H1 / 32), dim3(32, 8)>>>(W2);
    gemm1<<<dim3(H0 / 128, N_ROWS / 128), 256, sizeof(SM1)>>>(b1);
    gemm2_fused<<<dim3(1, N_ROWS / 64), 256, sizeof(SM2)>>>(b2, clusters, z, q);
}